// round 1
// baseline (speedup 1.0000x reference)
#include <cuda_runtime.h>
#include <cuda_bf16.h>
#include <cstdint>

// Problem constants
#define BATCH 256
#define TLEN  512
#define DDIM  256
#define NROWS (BATCH * TLEN)          // 131072 GEMM rows

// GEMM tiling
#define BM 64
#define BN 256
#define BK 32
#define LDA 33   // padded smem stride (floats) for A tile
#define LDB 33   // padded smem stride (floats) for W tile

// scratch for scores / attention weights (static device array: no allocation)
__device__ float g_scores[NROWS];

__device__ __forceinline__ unsigned f2tf32(float x) {
    unsigned u;
    asm("cvt.rna.tf32.f32 %0, %1;" : "=r"(u) : "f"(x));
    return u;
}

__device__ __forceinline__ void mma_tf32(float c[4],
                                         unsigned a0, unsigned a1, unsigned a2, unsigned a3,
                                         unsigned b0, unsigned b1) {
    asm volatile(
        "mma.sync.aligned.m16n8k8.row.col.f32.tf32.tf32.f32 "
        "{%0,%1,%2,%3}, {%4,%5,%6,%7}, {%8,%9}, {%0,%1,%2,%3};\n"
        : "+f"(c[0]), "+f"(c[1]), "+f"(c[2]), "+f"(c[3])
        : "r"(a0), "r"(a1), "r"(a2), "r"(a3), "r"(b0), "r"(b1));
}

// accurate-enough fast tanh: (e^{2x}-1)/(e^{2x}+1), rel err ~1e-6
__device__ __forceinline__ float tanh_fast(float x) {
    x = fminf(fmaxf(x, -15.f), 15.f);
    float e = __expf(2.f * x);
    return (e - 1.f) / (e + 1.f);
}

// ---------------------------------------------------------------------------
// Kernel 1: scores[b*T+t] = sum_e tanh( (ip @ W^T)[row,e] + bias[e] ) * ctx[e]
// GEMM M=131072, N=256 (full N per block), K=256, tf32 tensor cores.
// ---------------------------------------------------------------------------
__global__ __launch_bounds__(256) void scores_kernel(
    const float* __restrict__ ip,    // [NROWS, 256]
    const float* __restrict__ W,     // [256, 256]  (W[e][d], row-major over d)
    const float* __restrict__ bias,  // [256]
    const float* __restrict__ ctx)   // [256] (context[:,0])
{
    __shared__ unsigned sA[BM * LDA];
    __shared__ unsigned sB[BN * LDB];
    __shared__ float    sbias[BN];
    __shared__ float    sctx[BN];

    const int tid  = threadIdx.x;
    const int warp = tid >> 5;
    const int lane = tid & 31;
    const int rowBase = blockIdx.x * BM;

    // bias/ctx to smem once
    sbias[tid] = bias[tid];
    sctx[tid]  = ctx[tid];

    float acc[4][4][4];   // [mtile][ntile][frag]
#pragma unroll
    for (int mt = 0; mt < 4; mt++)
#pragma unroll
        for (int nt = 0; nt < 4; nt++)
#pragma unroll
            for (int i = 0; i < 4; i++) acc[mt][nt][i] = 0.f;

    for (int k0 = 0; k0 < DDIM; k0 += BK) {
        // load A tile: 64 x 32 fp32 -> tf32 in smem (512 float4, 2/thread)
#pragma unroll
        for (int i = 0; i < 2; i++) {
            int f  = tid + i * 256;
            int r  = f >> 3;
            int c4 = (f & 7) * 4;
            float4 v = *(const float4*)(ip + (size_t)(rowBase + r) * DDIM + k0 + c4);
            sA[r * LDA + c4 + 0] = f2tf32(v.x);
            sA[r * LDA + c4 + 1] = f2tf32(v.y);
            sA[r * LDA + c4 + 2] = f2tf32(v.z);
            sA[r * LDA + c4 + 3] = f2tf32(v.w);
        }
        // load W tile: 256 x 32 (2048 float4, 8/thread)
#pragma unroll
        for (int i = 0; i < 8; i++) {
            int f  = tid + i * 256;
            int r  = f >> 3;
            int c4 = (f & 7) * 4;
            float4 v = *(const float4*)(W + (size_t)r * DDIM + k0 + c4);
            sB[r * LDB + c4 + 0] = f2tf32(v.x);
            sB[r * LDB + c4 + 1] = f2tf32(v.y);
            sB[r * LDB + c4 + 2] = f2tf32(v.z);
            sB[r * LDB + c4 + 3] = f2tf32(v.w);
        }
        __syncthreads();

        const int wn = warp * 32;
#pragma unroll
        for (int ks = 0; ks < 4; ks++) {
            const int kk = ks * 8;
            unsigned a[4][4];
#pragma unroll
            for (int mt = 0; mt < 4; mt++) {
                int r = mt * 16 + (lane >> 2);
                int c = kk + (lane & 3);
                a[mt][0] = sA[r * LDA + c];
                a[mt][1] = sA[(r + 8) * LDA + c];
                a[mt][2] = sA[r * LDA + c + 4];
                a[mt][3] = sA[(r + 8) * LDA + c + 4];
            }
#pragma unroll
            for (int nt = 0; nt < 4; nt++) {
                int n = wn + nt * 8 + (lane >> 2);
                int c = kk + (lane & 3);
                unsigned b0 = sB[n * LDB + c];
                unsigned b1 = sB[n * LDB + c + 4];
#pragma unroll
                for (int mt = 0; mt < 4; mt++)
                    mma_tf32(acc[mt][nt], a[mt][0], a[mt][1], a[mt][2], a[mt][3], b0, b1);
            }
        }
        __syncthreads();
    }

    // ---- epilogue: score_row = sum_cols tanh(acc + bias)*ctx ----
    const int g  = lane >> 2;   // 0..7
    const int tg = lane & 3;    // 0..3

    float rs[8];
#pragma unroll
    for (int i = 0; i < 8; i++) rs[i] = 0.f;

#pragma unroll
    for (int nt = 0; nt < 4; nt++) {
        int col = warp * 32 + nt * 8 + 2 * tg;
        float b0 = sbias[col],     b1 = sbias[col + 1];
        float c0 = sctx[col],      c1 = sctx[col + 1];
#pragma unroll
        for (int mt = 0; mt < 4; mt++) {
            rs[2 * mt]     += tanh_fast(acc[mt][nt][0] + b0) * c0
                            + tanh_fast(acc[mt][nt][1] + b1) * c1;
            rs[2 * mt + 1] += tanh_fast(acc[mt][nt][2] + b0) * c0
                            + tanh_fast(acc[mt][nt][3] + b1) * c1;
        }
    }
    // reduce across the 4 lanes sharing each row
#pragma unroll
    for (int off = 1; off <= 2; off <<= 1)
#pragma unroll
        for (int i = 0; i < 8; i++)
            rs[i] += __shfl_xor_sync(0xffffffffu, rs[i], off);

    // deterministic cross-warp reduce; reuse sA space (done with it after last sync)
    float* spart = reinterpret_cast<float*>(sA);   // [8 warps][64 rows]
    if (tg == 0) {
#pragma unroll
        for (int mt = 0; mt < 4; mt++) {
            spart[warp * 64 + mt * 16 + g]     = rs[2 * mt];
            spart[warp * 64 + mt * 16 + 8 + g] = rs[2 * mt + 1];
        }
    }
    __syncthreads();
    if (tid < BM) {
        float s = 0.f;
#pragma unroll
        for (int w = 0; w < 8; w++) s += spart[w * 64 + tid];
        g_scores[rowBase + tid] = s;
    }
}

// ---------------------------------------------------------------------------
// Kernel 2: per-batch softmax over T, then out[b,d] = sum_t attn[b,t]*ip[b,t,d]
// ---------------------------------------------------------------------------
__global__ __launch_bounds__(256) void out_kernel(
    const float* __restrict__ ip, float* __restrict__ out)
{
    __shared__ float attn[TLEN];
    __shared__ float redm[8];
    __shared__ float reds[8];

    const int b = blockIdx.x;
    const int tid = threadIdx.x;
    const int warp = tid >> 5;
    const int lane = tid & 31;

    const float* sc = g_scores + (size_t)b * TLEN;
    float s0 = sc[tid];
    float s1 = sc[tid + 256];

    // block max
    float m = fmaxf(s0, s1);
#pragma unroll
    for (int o = 16; o > 0; o >>= 1) m = fmaxf(m, __shfl_xor_sync(0xffffffffu, m, o));
    if (lane == 0) redm[warp] = m;
    __syncthreads();
    float bm = redm[0];
#pragma unroll
    for (int w = 1; w < 8; w++) bm = fmaxf(bm, redm[w]);

    float e0 = __expf(s0 - bm);
    float e1 = __expf(s1 - bm);
    attn[tid]       = e0;
    attn[tid + 256] = e1;

    float su = e0 + e1;
#pragma unroll
    for (int o = 16; o > 0; o >>= 1) su += __shfl_xor_sync(0xffffffffu, su, o);
    if (lane == 0) reds[warp] = su;
    __syncthreads();   // also makes attn[] fully visible
    float tot = 0.f;
#pragma unroll
    for (int w = 0; w < 8; w++) tot += reds[w];
    float inv = 1.f / tot;

    // weighted sum over t; thread owns column d = tid (coalesced across warp)
    const float* base = ip + ((size_t)b * TLEN) * DDIM + tid;
    float acc = 0.f;
#pragma unroll 8
    for (int t = 0; t < TLEN; t++)
        acc = fmaf(attn[t], base[(size_t)t * DDIM], acc);

    out[(size_t)b * DDIM + tid] = acc * inv;
}

// ---------------------------------------------------------------------------
extern "C" void kernel_launch(void* const* d_in, const int* in_sizes, int n_in,
                              void* d_out, int out_size)
{
    const float* ip   = (const float*)d_in[0];   // [256,512,256]
    const float* W    = (const float*)d_in[1];   // [256,256]
    const float* bias = (const float*)d_in[2];   // [256]
    const float* ctx  = (const float*)d_in[3];   // [256,1]
    float* out = (float*)d_out;                  // [256,256]

    scores_kernel<<<NROWS / BM, 256>>>(ip, W, bias, ctx);
    out_kernel<<<BATCH, 256>>>(ip, out);
}

// round 2
// speedup vs baseline: 1.9836x; 1.9836x over previous
#include <cuda_runtime.h>
#include <cuda_bf16.h>
#include <cstdint>

// Problem constants
#define BATCH 256
#define TLEN  512
#define DDIM  256
#define NROWS (BATCH * TLEN)

// GEMM tiling
#define BM 128
#define BN 256
#define BK 32
#define NTHREADS 512

// smem layout (dynamic), in bytes
#define SA_BYTES (BM * BK * 4)          // 16384
#define SB_BYTES (BN * BK * 4)          // 32768
#define OFF_A0 0
#define OFF_A1 (SA_BYTES)
#define OFF_B0 (2 * SA_BYTES)
#define OFF_B1 (2 * SA_BYTES + SB_BYTES)
#define OFF_SPART (2 * SA_BYTES + 2 * SB_BYTES)   // 16 warps * 64 rows * 4B = 4KB
#define SMEM_BYTES (OFF_SPART + 16 * 64 * 4)      // 102400

// scratch (static device arrays: no allocation)
__device__ float g_scores[NROWS];
__device__ float g_part[4][BATCH][DDIM];

__device__ __forceinline__ void cpa16(void* smem, const void* gmem) {
    unsigned s = (unsigned)__cvta_generic_to_shared(smem);
    asm volatile("cp.async.cg.shared.global [%0], [%1], 16;\n" :: "r"(s), "l"(gmem));
}
__device__ __forceinline__ void cpa_commit() {
    asm volatile("cp.async.commit_group;\n");
}
template <int N>
__device__ __forceinline__ void cpa_wait() {
    asm volatile("cp.async.wait_group %0;\n" :: "n"(N));
}

__device__ __forceinline__ void mma_tf32(float c[4],
                                         unsigned a0, unsigned a1, unsigned a2, unsigned a3,
                                         unsigned b0, unsigned b1) {
    asm volatile(
        "mma.sync.aligned.m16n8k8.row.col.f32.tf32.tf32.f32 "
        "{%0,%1,%2,%3}, {%4,%5,%6,%7}, {%8,%9}, {%0,%1,%2,%3};\n"
        : "+f"(c[0]), "+f"(c[1]), "+f"(c[2]), "+f"(c[3])
        : "r"(a0), "r"(a1), "r"(a2), "r"(a3), "r"(b0), "r"(b1));
}

__device__ __forceinline__ float tanh_fast(float x) {
    x = fminf(fmaxf(x, -15.f), 15.f);
    float e = __expf(2.f * x);
    return (e - 1.f) / (e + 1.f);
}

// swizzled smem float index for (row, float-col c within 0..31):
// 16B chunk cc = c>>2 stored at chunk cc ^ (row & 7)
__device__ __forceinline__ int swz(int row, int chunk, int within) {
    return row * BK + ((chunk ^ (row & 7)) << 2) + within;
}

// ---------------------------------------------------------------------------
// Kernel 1: fused GEMM (tf32 tensor cores, raw fp32 operands -> HW truncation)
// + tanh + context dot -> g_scores. Double-buffered cp.async pipeline.
// ---------------------------------------------------------------------------
__global__ void __launch_bounds__(NTHREADS, 1) scores_kernel(
    const float* __restrict__ ip,    // [NROWS, 256]
    const float* __restrict__ W,     // [256, 256]
    const float* __restrict__ bias,  // [256]
    const float* __restrict__ ctx)   // [256]
{
    extern __shared__ char smem[];
    __shared__ float sbias[BN];
    __shared__ float sctx[BN];

    const int tid   = threadIdx.x;
    const int warp  = tid >> 5;
    const int lane  = tid & 31;
    const int g     = lane >> 2;   // 0..7
    const int tg    = lane & 3;    // 0..3
    const int mhalf = warp >> 3;   // 0..1 (64-row half)
    const int nwarp = warp & 7;    // 0..7 (32-col group)
    const int wn    = nwarp * 32;
    const int rowBase = blockIdx.x * BM;

    if (tid < BN) { sbias[tid] = bias[tid]; sctx[tid] = ctx[tid]; }

    float acc[4][4][4];
#pragma unroll
    for (int mt = 0; mt < 4; mt++)
#pragma unroll
        for (int nt = 0; nt < 4; nt++)
#pragma unroll
            for (int i = 0; i < 4; i++) acc[mt][nt][i] = 0.f;

    // stage issue: copy A(BM x 32) + W(BN x 32) chunk for k0 = c*32 into buffer bsel
    auto issue = [&](int c, int bsel) {
        const int k0 = c * BK;
        char* sA = smem + (bsel ? OFF_A1 : OFF_A0);
        char* sB = smem + (bsel ? OFF_B1 : OFF_B0);
        // A: 128 rows x 8 chunks = 1024 chunks, 2 per thread
#pragma unroll
        for (int i = 0; i < 2; i++) {
            int f = tid + i * NTHREADS;
            int r = f >> 3, cc = f & 7;
            cpa16(sA + (size_t)(r * BK + ((cc ^ (r & 7)) << 2)) * 4,
                  ip + (size_t)(rowBase + r) * DDIM + k0 + cc * 4);
        }
        // B: 256 rows x 8 chunks = 2048 chunks, 4 per thread
#pragma unroll
        for (int i = 0; i < 4; i++) {
            int f = tid + i * NTHREADS;
            int r = f >> 3, cc = f & 7;
            cpa16(sB + (size_t)(r * BK + ((cc ^ (r & 7)) << 2)) * 4,
                  W + (size_t)r * DDIM + k0 + cc * 4);
        }
    };

    issue(0, 0); cpa_commit();
    issue(1, 1); cpa_commit();

    const int NCHUNK = DDIM / BK;   // 8
    for (int c = 0; c < NCHUNK; c++) {
        cpa_wait<1>();
        __syncthreads();

        const unsigned* sA = (const unsigned*)(smem + ((c & 1) ? OFF_A1 : OFF_A0));
        const unsigned* sB = (const unsigned*)(smem + ((c & 1) ? OFF_B1 : OFF_B0));

#pragma unroll
        for (int ks = 0; ks < 4; ks++) {
            const int kc = ks * 2;   // chunk index pair (kk = ks*8)
            unsigned a[4][4];
#pragma unroll
            for (int mt = 0; mt < 4; mt++) {
                int r = mhalf * 64 + mt * 16 + g;
                a[mt][0] = sA[swz(r,     kc,     tg)];
                a[mt][1] = sA[swz(r + 8, kc,     tg)];
                a[mt][2] = sA[swz(r,     kc + 1, tg)];
                a[mt][3] = sA[swz(r + 8, kc + 1, tg)];
            }
#pragma unroll
            for (int nt = 0; nt < 4; nt++) {
                int n = wn + nt * 8 + g;
                unsigned b0 = sB[swz(n, kc,     tg)];
                unsigned b1 = sB[swz(n, kc + 1, tg)];
#pragma unroll
                for (int mt = 0; mt < 4; mt++)
                    mma_tf32(acc[mt][nt], a[mt][0], a[mt][1], a[mt][2], a[mt][3], b0, b1);
            }
        }
        __syncthreads();
        if (c + 2 < NCHUNK) issue(c + 2, c & 1);
        cpa_commit();
    }

    // ---- epilogue: row score = sum_cols tanh(acc + bias) * ctx ----
    float rs[8];
#pragma unroll
    for (int i = 0; i < 8; i++) rs[i] = 0.f;

#pragma unroll
    for (int nt = 0; nt < 4; nt++) {
        int col = wn + nt * 8 + 2 * tg;
        float b0 = sbias[col], b1 = sbias[col + 1];
        float c0 = sctx[col],  c1 = sctx[col + 1];
#pragma unroll
        for (int mt = 0; mt < 4; mt++) {
            rs[2 * mt]     += tanh_fast(acc[mt][nt][0] + b0) * c0
                            + tanh_fast(acc[mt][nt][1] + b1) * c1;
            rs[2 * mt + 1] += tanh_fast(acc[mt][nt][2] + b0) * c0
                            + tanh_fast(acc[mt][nt][3] + b1) * c1;
        }
    }
#pragma unroll
    for (int off = 1; off <= 2; off <<= 1)
#pragma unroll
        for (int i = 0; i < 8; i++)
            rs[i] += __shfl_xor_sync(0xffffffffu, rs[i], off);

    float* spart = (float*)(smem + OFF_SPART);   // [16 warps][64 rows]
    if (tg == 0) {
#pragma unroll
        for (int mt = 0; mt < 4; mt++) {
            spart[warp * 64 + mt * 16 + g]     = rs[2 * mt];
            spart[warp * 64 + mt * 16 + 8 + g] = rs[2 * mt + 1];
        }
    }
    __syncthreads();
    if (tid < BM) {
        int mh = tid >> 6, row = tid & 63;
        float s = 0.f;
#pragma unroll
        for (int w = 0; w < 8; w++) s += spart[(mh * 8 + w) * 64 + row];
        g_scores[rowBase + tid] = s;
    }
}

// ---------------------------------------------------------------------------
// Kernel 2: softmax (redundant per t-slice, cheap) + partial weighted sums
// grid (BATCH, 4); each block handles 128 t's.
// ---------------------------------------------------------------------------
__global__ __launch_bounds__(256) void out_partial_kernel(
    const float* __restrict__ ip)
{
    __shared__ float attn[TLEN];
    __shared__ float redm[8];
    __shared__ float reds[8];

    const int b = blockIdx.x;
    const int q = blockIdx.y;
    const int tid = threadIdx.x;
    const int warp = tid >> 5;
    const int lane = tid & 31;

    const float* sc = g_scores + (size_t)b * TLEN;
    float s0 = sc[tid];
    float s1 = sc[tid + 256];

    float m = fmaxf(s0, s1);
#pragma unroll
    for (int o = 16; o > 0; o >>= 1) m = fmaxf(m, __shfl_xor_sync(0xffffffffu, m, o));
    if (lane == 0) redm[warp] = m;
    __syncthreads();
    float bm = redm[0];
#pragma unroll
    for (int w = 1; w < 8; w++) bm = fmaxf(bm, redm[w]);

    float e0 = __expf(s0 - bm);
    float e1 = __expf(s1 - bm);
    attn[tid]       = e0;
    attn[tid + 256] = e1;

    float su = e0 + e1;
#pragma unroll
    for (int o = 16; o > 0; o >>= 1) su += __shfl_xor_sync(0xffffffffu, su, o);
    if (lane == 0) reds[warp] = su;
    __syncthreads();
    float tot = 0.f;
#pragma unroll
    for (int w = 0; w < 8; w++) tot += reds[w];
    float inv = 1.f / tot;

    const int t0 = q * 128;
    const float* base = ip + ((size_t)b * TLEN + t0) * DDIM + tid;
    float acc = 0.f;
#pragma unroll 8
    for (int t = 0; t < 128; t++)
        acc = fmaf(attn[t0 + t], base[(size_t)t * DDIM], acc);

    g_part[q][b][tid] = acc * inv;
}

__global__ __launch_bounds__(256) void combine_kernel(float* __restrict__ out)
{
    const int b = blockIdx.x;
    const int d = threadIdx.x;
    out[(size_t)b * DDIM + d] = g_part[0][b][d] + g_part[1][b][d]
                              + g_part[2][b][d] + g_part[3][b][d];
}

// ---------------------------------------------------------------------------
extern "C" void kernel_launch(void* const* d_in, const int* in_sizes, int n_in,
                              void* d_out, int out_size)
{
    const float* ip   = (const float*)d_in[0];
    const float* W    = (const float*)d_in[1];
    const float* bias = (const float*)d_in[2];
    const float* ctx  = (const float*)d_in[3];
    float* out = (float*)d_out;

    cudaFuncSetAttribute(scores_kernel,
                         cudaFuncAttributeMaxDynamicSharedMemorySize, SMEM_BYTES);

    scores_kernel<<<NROWS / BM, NTHREADS, SMEM_BYTES>>>(ip, W, bias, ctx);
    dim3 gp(BATCH, 4);
    out_partial_kernel<<<gp, 256>>>(ip);
    combine_kernel<<<BATCH, 256>>>(out);
}

// round 4
// speedup vs baseline: 2.3950x; 1.2074x over previous
#include <cuda_runtime.h>
#include <cuda_bf16.h>
#include <cstdint>

// Problem constants
#define BATCH 256
#define TLEN  512
#define DDIM  256
#define NROWS (BATCH * TLEN)

// GEMM tiling
#define BM 128
#define BN 256
#define BK 32
#define NTHREADS 512
#define STAGES 4
#define NCHUNK (DDIM / BK)    // 8

// smem layout (dynamic), bytes
#define SA_BYTES (BM * BK * 4)              // 16384
#define SB_BYTES (BN * BK * 4)              // 32768
#define STAGE_BYTES (SA_BYTES + SB_BYTES)   // 49152
#define OFF_SPART (STAGES * STAGE_BYTES)    // 196608
#define SMEM_BYTES (OFF_SPART + 16 * 64 * 4)  // 200704

// scratch (static device arrays: no allocation)
__device__ float g_scores[NROWS];
__device__ float g_part[4][BATCH][DDIM];

__device__ __forceinline__ void cpa16(void* smem, const void* gmem) {
    unsigned s = (unsigned)__cvta_generic_to_shared(smem);
    asm volatile("cp.async.cg.shared.global [%0], [%1], 16;\n" :: "r"(s), "l"(gmem));
}
__device__ __forceinline__ void cpa_commit() {
    asm volatile("cp.async.commit_group;\n");
}
template <int N>
__device__ __forceinline__ void cpa_wait() {
    asm volatile("cp.async.wait_group %0;\n" :: "n"(N));
}

__device__ __forceinline__ void mma_tf32(float c[4],
                                         unsigned a0, unsigned a1, unsigned a2, unsigned a3,
                                         unsigned b0, unsigned b1) {
    asm volatile(
        "mma.sync.aligned.m16n8k8.row.col.f32.tf32.tf32.f32 "
        "{%0,%1,%2,%3}, {%4,%5,%6,%7}, {%8,%9}, {%0,%1,%2,%3};\n"
        : "+f"(c[0]), "+f"(c[1]), "+f"(c[2]), "+f"(c[3])
        : "r"(a0), "r"(a1), "r"(a2), "r"(a3), "r"(b0), "r"(b1));
}

__device__ __forceinline__ float tanh_fast(float x) {
    x = fminf(fmaxf(x, -15.f), 15.f);
    float e = __expf(2.f * x);
    return __fdividef(e - 1.f, e + 1.f);
}

// swizzled smem float index: 16B chunk cc stored at chunk cc ^ (row & 7)
__device__ __forceinline__ int swz(int row, int chunk, int within) {
    return row * BK + ((chunk ^ (row & 7)) << 2) + within;
}

// ---------------------------------------------------------------------------
// Kernel 1: fused tf32 tensor-core GEMM + tanh + context dot -> g_scores.
// 4-stage cp.async ring, ONE __syncthreads per K-chunk.
// ---------------------------------------------------------------------------
__global__ void __launch_bounds__(NTHREADS, 1) scores_kernel(
    const float* __restrict__ ip,    // [NROWS, 256]
    const float* __restrict__ W,     // [256, 256]
    const float* __restrict__ bias,  // [256]
    const float* __restrict__ ctx)   // [256]
{
    extern __shared__ char smem[];
    __shared__ float sbias[BN];
    __shared__ float sctx[BN];

    const int tid   = threadIdx.x;
    const int warp  = tid >> 5;
    const int lane  = tid & 31;
    const int g     = lane >> 2;   // 0..7
    const int tg    = lane & 3;    // 0..3
    const int mhalf = warp >> 3;   // 0..1 (64-row half)
    const int nwarp = warp & 7;    // 0..7 (32-col group)
    const int wn    = nwarp * 32;
    const int rowBase = blockIdx.x * BM;

    if (tid < BN) { sbias[tid] = bias[tid]; sctx[tid] = ctx[tid]; }

    float acc[4][4][4];
#pragma unroll
    for (int mt = 0; mt < 4; mt++)
#pragma unroll
        for (int nt = 0; nt < 4; nt++)
#pragma unroll
            for (int i = 0; i < 4; i++) acc[mt][nt][i] = 0.f;

    // stage loader: K-chunk c -> ring buffer c % STAGES
    auto issue = [&](int c) {
        const int k0 = c * BK;
        char* sA = smem + (c & (STAGES - 1)) * STAGE_BYTES;
        char* sB = sA + SA_BYTES;
        // A: 128 rows x 8 16B-chunks = 1024, 2 per thread
#pragma unroll
        for (int i = 0; i < 2; i++) {
            int f = tid + i * NTHREADS;
            int r = f >> 3, cc = f & 7;
            cpa16(sA + (size_t)(r * BK + ((cc ^ (r & 7)) << 2)) * 4,
                  ip + (size_t)(rowBase + r) * DDIM + k0 + cc * 4);
        }
        // B: 256 rows x 8 = 2048, 4 per thread
#pragma unroll
        for (int i = 0; i < 4; i++) {
            int f = tid + i * NTHREADS;
            int r = f >> 3, cc = f & 7;
            cpa16(sB + (size_t)(r * BK + ((cc ^ (r & 7)) << 2)) * 4,
                  W + (size_t)r * DDIM + k0 + cc * 4);
        }
    };

#pragma unroll
    for (int c = 0; c < STAGES - 1; c++) { issue(c); cpa_commit(); }

    for (int c = 0; c < NCHUNK; c++) {
        cpa_wait<STAGES - 2>();   // chunk c resident
        __syncthreads();          // all warps see it; buffer (c-1)%4 free for reuse

        const unsigned* sA =
            (const unsigned*)(smem + (c & (STAGES - 1)) * STAGE_BYTES);
        const unsigned* sB = sA + SA_BYTES / 4;

#pragma unroll
        for (int ks = 0; ks < 4; ks++) {
            const int kc = ks * 2;
            unsigned a[4][4];
#pragma unroll
            for (int mt = 0; mt < 4; mt++) {
                int r = mhalf * 64 + mt * 16 + g;
                a[mt][0] = sA[swz(r,     kc,     tg)];
                a[mt][1] = sA[swz(r + 8, kc,     tg)];
                a[mt][2] = sA[swz(r,     kc + 1, tg)];
                a[mt][3] = sA[swz(r + 8, kc + 1, tg)];
            }
#pragma unroll
            for (int nt = 0; nt < 4; nt++) {
                int n = wn + nt * 8 + g;
                unsigned b0 = sB[swz(n, kc,     tg)];
                unsigned b1 = sB[swz(n, kc + 1, tg)];
#pragma unroll
                for (int mt = 0; mt < 4; mt++)
                    mma_tf32(acc[mt][nt], a[mt][0], a[mt][1], a[mt][2], a[mt][3], b0, b1);
            }
        }

        if (c + STAGES - 1 < NCHUNK) issue(c + STAGES - 1);
        cpa_commit();             // commit (possibly empty) to keep group counting uniform
    }

    // ---- epilogue: row score = sum_cols tanh(acc + bias) * ctx ----
    float rs[8];
#pragma unroll
    for (int i = 0; i < 8; i++) rs[i] = 0.f;

#pragma unroll
    for (int nt = 0; nt < 4; nt++) {
        int col = wn + nt * 8 + 2 * tg;
        float b0 = sbias[col], b1 = sbias[col + 1];
        float c0 = sctx[col],  c1 = sctx[col + 1];
#pragma unroll
        for (int mt = 0; mt < 4; mt++) {
            rs[2 * mt]     += tanh_fast(acc[mt][nt][0] + b0) * c0
                            + tanh_fast(acc[mt][nt][1] + b1) * c1;
            rs[2 * mt + 1] += tanh_fast(acc[mt][nt][2] + b0) * c0
                            + tanh_fast(acc[mt][nt][3] + b1) * c1;
        }
    }
#pragma unroll
    for (int off = 1; off <= 2; off <<= 1)
#pragma unroll
        for (int i = 0; i < 8; i++)
            rs[i] += __shfl_xor_sync(0xffffffffu, rs[i], off);

    float* spart = (float*)(smem + OFF_SPART);   // [16 warps][64 rows]
    __syncthreads();                              // done with ring buffers
    if (tg == 0) {
#pragma unroll
        for (int mt = 0; mt < 4; mt++) {
            spart[warp * 64 + mt * 16 + g]     = rs[2 * mt];
            spart[warp * 64 + mt * 16 + 8 + g] = rs[2 * mt + 1];
        }
    }
    __syncthreads();
    if (tid < BM) {
        int mh = tid >> 6, row = tid & 63;
        float s = 0.f;
#pragma unroll
        for (int w = 0; w < 8; w++) s += spart[(mh * 8 + w) * 64 + row];
        g_scores[rowBase + tid] = s;
    }
}

// ---------------------------------------------------------------------------
// Kernel 2: softmax (redundant per t-slice, cheap) + partial weighted sums
// ---------------------------------------------------------------------------
__global__ __launch_bounds__(256) void out_partial_kernel(
    const float* __restrict__ ip)
{
    __shared__ float attn[TLEN];
    __shared__ float redm[8];
    __shared__ float reds[8];

    const int b = blockIdx.x;
    const int q = blockIdx.y;
    const int tid = threadIdx.x;
    const int warp = tid >> 5;
    const int lane = tid & 31;

    const float* sc = g_scores + (size_t)b * TLEN;
    float s0 = sc[tid];
    float s1 = sc[tid + 256];

    float m = fmaxf(s0, s1);
#pragma unroll
    for (int o = 16; o > 0; o >>= 1) m = fmaxf(m, __shfl_xor_sync(0xffffffffu, m, o));
    if (lane == 0) redm[warp] = m;
    __syncthreads();
    float bm = redm[0];
#pragma unroll
    for (int w = 1; w < 8; w++) bm = fmaxf(bm, redm[w]);

    float e0 = __expf(s0 - bm);
    float e1 = __expf(s1 - bm);
    attn[tid]       = e0;
    attn[tid + 256] = e1;

    float su = e0 + e1;
#pragma unroll
    for (int o = 16; o > 0; o >>= 1) su += __shfl_xor_sync(0xffffffffu, su, o);
    if (lane == 0) reds[warp] = su;
    __syncthreads();
    float tot = 0.f;
#pragma unroll
    for (int w = 0; w < 8; w++) tot += reds[w];
    float inv = 1.f / tot;

    const int t0 = q * 128;
    const float* base = ip + ((size_t)b * TLEN + t0) * DDIM + tid;
    float acc = 0.f;
#pragma unroll 8
    for (int t = 0; t < 128; t++)
        acc = fmaf(attn[t0 + t], base[(size_t)t * DDIM], acc);

    g_part[q][b][tid] = acc * inv;
}

__global__ __launch_bounds__(256) void combine_kernel(float* __restrict__ out)
{
    const int b = blockIdx.x;
    const int d = threadIdx.x;
    out[(size_t)b * DDIM + d] = g_part[0][b][d] + g_part[1][b][d]
                              + g_part[2][b][d] + g_part[3][b][d];
}

// ---------------------------------------------------------------------------
extern "C" void kernel_launch(void* const* d_in, const int* in_sizes, int n_in,
                              void* d_out, int out_size)
{
    const float* ip   = (const float*)d_in[0];
    const float* W    = (const float*)d_in[1];
    const float* bias = (const float*)d_in[2];
    const float* ctx  = (const float*)d_in[3];
    float* out = (float*)d_out;

    cudaFuncSetAttribute(scores_kernel,
                         cudaFuncAttributeMaxDynamicSharedMemorySize, SMEM_BYTES);

    scores_kernel<<<NROWS / BM, NTHREADS, SMEM_BYTES>>>(ip, W, bias, ctx);
    dim3 gp(BATCH, 4);
    out_partial_kernel<<<gp, 256>>>(ip);
    combine_kernel<<<BATCH, 256>>>(out);
}

// round 5
// speedup vs baseline: 2.4328x; 1.0158x over previous
#include <cuda_runtime.h>
#include <cuda_bf16.h>
#include <cstdint>

// Problem constants
#define BATCH 256
#define TLEN  512
#define DDIM  256
#define NROWS (BATCH * TLEN)

// GEMM tiling
#define BM 128
#define BN 256
#define BK 32
#define NTHREADS 512
#define STAGES 4
#define NCHUNK (DDIM / BK)    // 8

// smem layout (dynamic), bytes
#define SA_BYTES (BM * BK * 4)              // 16384
#define SB_BYTES (BN * BK * 4)              // 32768
#define STAGE_BYTES (SA_BYTES + SB_BYTES)   // 49152
#define OFF_SPART (STAGES * STAGE_BYTES)    // 196608
#define SMEM_BYTES (OFF_SPART + 16 * 64 * 4)  // 200704

// scratch (static device arrays: no allocation)
__device__ float g_scores[NROWS];
__device__ float g_part[4][BATCH][DDIM];

__device__ __forceinline__ void cpa16(void* smem, const void* gmem) {
    unsigned s = (unsigned)__cvta_generic_to_shared(smem);
    asm volatile("cp.async.cg.shared.global [%0], [%1], 16;\n" :: "r"(s), "l"(gmem));
}
__device__ __forceinline__ void cpa_commit() {
    asm volatile("cp.async.commit_group;\n");
}
template <int N>
__device__ __forceinline__ void cpa_wait() {
    asm volatile("cp.async.wait_group %0;\n" :: "n"(N));
}

__device__ __forceinline__ void ldsm_x4(unsigned r[4], unsigned addr) {
    asm volatile(
        "ldmatrix.sync.aligned.m8n8.x4.shared.b16 {%0,%1,%2,%3}, [%4];"
        : "=r"(r[0]), "=r"(r[1]), "=r"(r[2]), "=r"(r[3]) : "r"(addr));
}
__device__ __forceinline__ void ldsm_x2(unsigned& r0, unsigned& r1, unsigned addr) {
    asm volatile(
        "ldmatrix.sync.aligned.m8n8.x2.shared.b16 {%0,%1}, [%2];"
        : "=r"(r0), "=r"(r1) : "r"(addr));
}

__device__ __forceinline__ void mma_tf32(float c[4],
                                         unsigned a0, unsigned a1, unsigned a2, unsigned a3,
                                         unsigned b0, unsigned b1) {
    asm volatile(
        "mma.sync.aligned.m16n8k8.row.col.f32.tf32.tf32.f32 "
        "{%0,%1,%2,%3}, {%4,%5,%6,%7}, {%8,%9}, {%0,%1,%2,%3};\n"
        : "+f"(c[0]), "+f"(c[1]), "+f"(c[2]), "+f"(c[3])
        : "r"(a0), "r"(a1), "r"(a2), "r"(a3), "r"(b0), "r"(b1));
}

__device__ __forceinline__ float tanh_fast(float x) {
    x = fminf(fmaxf(x, -15.f), 15.f);
    float e = __expf(2.f * x);
    return __fdividef(e - 1.f, e + 1.f);
}

// ---------------------------------------------------------------------------
// Kernel 1: fused tf32 tensor-core GEMM (ldmatrix operand path) + tanh +
// context dot -> g_scores. 4-stage cp.async ring, one barrier per K-chunk.
// ---------------------------------------------------------------------------
__global__ void __launch_bounds__(NTHREADS, 1) scores_kernel(
    const float* __restrict__ ip,    // [NROWS, 256]
    const float* __restrict__ W,     // [256, 256]
    const float* __restrict__ bias,  // [256]
    const float* __restrict__ ctx)   // [256]
{
    extern __shared__ char smem[];
    __shared__ float sbias[BN];
    __shared__ float sctx[BN];

    const int tid   = threadIdx.x;
    const int warp  = tid >> 5;
    const int lane  = tid & 31;
    const int g     = lane >> 2;   // 0..7
    const int tg    = lane & 3;    // 0..3
    const int mhalf = warp >> 3;   // 0..1 (64-row half)
    const int nwarp = warp & 7;    // 0..7 (32-col group)
    const int wn    = nwarp * 32;
    const int rowBase = blockIdx.x * BM;

    if (tid < BN) { sbias[tid] = bias[tid]; sctx[tid] = ctx[tid]; }

    // lane-constant LDSM addressing pieces
    const int s7   = lane & 7;                       // swizzle key (rows 8-aligned)
    const int c0a  = lane >> 4;                      // A: matrices 2,3 -> chunk kc+1
    const unsigned aRowOff =
        (unsigned)((mhalf * 64 + ((lane >> 3) & 1) * 8 + s7) * 128);
    const int cbm  = (lane >> 3) & 1;                // B: matrix 1 -> chunk kc+1
    const unsigned bRowOff0 = (unsigned)((wn + s7) * 128);

    const unsigned smem_base = (unsigned)__cvta_generic_to_shared(smem);

    float acc[4][4][4];
#pragma unroll
    for (int mt = 0; mt < 4; mt++)
#pragma unroll
        for (int nt = 0; nt < 4; nt++)
#pragma unroll
            for (int i = 0; i < 4; i++) acc[mt][nt][i] = 0.f;

    // stage loader: K-chunk c -> ring buffer c % STAGES
    auto issue = [&](int c) {
        const int k0 = c * BK;
        char* sA = smem + (c & (STAGES - 1)) * STAGE_BYTES;
        char* sB = sA + SA_BYTES;
#pragma unroll
        for (int i = 0; i < 2; i++) {
            int f = tid + i * NTHREADS;
            int r = f >> 3, cc = f & 7;
            cpa16(sA + (size_t)(r * BK + ((cc ^ (r & 7)) << 2)) * 4,
                  ip + (size_t)(rowBase + r) * DDIM + k0 + cc * 4);
        }
#pragma unroll
        for (int i = 0; i < 4; i++) {
            int f = tid + i * NTHREADS;
            int r = f >> 3, cc = f & 7;
            cpa16(sB + (size_t)(r * BK + ((cc ^ (r & 7)) << 2)) * 4,
                  W + (size_t)r * DDIM + k0 + cc * 4);
        }
    };

#pragma unroll
    for (int c = 0; c < STAGES - 1; c++) { issue(c); cpa_commit(); }

    for (int c = 0; c < NCHUNK; c++) {
        cpa_wait<STAGES - 2>();   // chunk c resident
        __syncthreads();          // all warps see it; buffer (c-1)%4 reusable

        const unsigned sAu = smem_base + (unsigned)((c & (STAGES - 1)) * STAGE_BYTES);
        const unsigned sBu = sAu + SB_BYTES ? sAu + SA_BYTES : sAu;  // sAu + SA_BYTES

#pragma unroll
        for (int ks = 0; ks < 4; ks++) {
            const int kc = ks * 2;
            unsigned a[4][4];
#pragma unroll
            for (int mt = 0; mt < 4; mt++) {
                unsigned addr = sAu + aRowOff + (unsigned)(mt * 2048)
                              + (unsigned)((((kc + c0a) ^ s7) << 4));
                ldsm_x4(a[mt], addr);
            }
#pragma unroll
            for (int nt = 0; nt < 4; nt++) {
                unsigned addr = sBu + bRowOff0 + (unsigned)(nt * 8 * 128)
                              + (unsigned)((((kc + cbm) ^ s7) << 4));
                unsigned b0, b1;
                ldsm_x2(b0, b1, addr);
#pragma unroll
                for (int mt = 0; mt < 4; mt++)
                    mma_tf32(acc[mt][nt], a[mt][0], a[mt][1], a[mt][2], a[mt][3], b0, b1);
            }
        }

        if (c + STAGES - 1 < NCHUNK) issue(c + STAGES - 1);
        cpa_commit();             // uniform group counting
    }

    // ---- epilogue: row score = sum_cols tanh(acc + bias) * ctx ----
    float rs[8];
#pragma unroll
    for (int i = 0; i < 8; i++) rs[i] = 0.f;

#pragma unroll
    for (int nt = 0; nt < 4; nt++) {
        int col = wn + nt * 8 + 2 * tg;
        float b0 = sbias[col], b1 = sbias[col + 1];
        float c0 = sctx[col],  c1 = sctx[col + 1];
#pragma unroll
        for (int mt = 0; mt < 4; mt++) {
            rs[2 * mt]     += tanh_fast(acc[mt][nt][0] + b0) * c0
                            + tanh_fast(acc[mt][nt][1] + b1) * c1;
            rs[2 * mt + 1] += tanh_fast(acc[mt][nt][2] + b0) * c0
                            + tanh_fast(acc[mt][nt][3] + b1) * c1;
        }
    }
#pragma unroll
    for (int off = 1; off <= 2; off <<= 1)
#pragma unroll
        for (int i = 0; i < 8; i++)
            rs[i] += __shfl_xor_sync(0xffffffffu, rs[i], off);

    float* spart = (float*)(smem + OFF_SPART);   // [16 warps][64 rows]
    __syncthreads();                              // done with ring buffers
    if (tg == 0) {
#pragma unroll
        for (int mt = 0; mt < 4; mt++) {
            spart[warp * 64 + mt * 16 + g]     = rs[2 * mt];
            spart[warp * 64 + mt * 16 + 8 + g] = rs[2 * mt + 1];
        }
    }
    __syncthreads();
    if (tid < BM) {
        int mh = tid >> 6, row = tid & 63;
        float s = 0.f;
#pragma unroll
        for (int w = 0; w < 8; w++) s += spart[(mh * 8 + w) * 64 + row];
        g_scores[rowBase + tid] = s;
    }
}

// ---------------------------------------------------------------------------
// Kernel 2: softmax (redundant per t-slice, cheap) + partial weighted sums
// ---------------------------------------------------------------------------
__global__ __launch_bounds__(256) void out_partial_kernel(
    const float* __restrict__ ip)
{
    __shared__ float attn[TLEN];
    __shared__ float redm[8];
    __shared__ float reds[8];

    const int b = blockIdx.x;
    const int q = blockIdx.y;
    const int tid = threadIdx.x;
    const int warp = tid >> 5;
    const int lane = tid & 31;

    const float* sc = g_scores + (size_t)b * TLEN;
    float s0 = sc[tid];
    float s1 = sc[tid + 256];

    float m = fmaxf(s0, s1);
#pragma unroll
    for (int o = 16; o > 0; o >>= 1) m = fmaxf(m, __shfl_xor_sync(0xffffffffu, m, o));
    if (lane == 0) redm[warp] = m;
    __syncthreads();
    float bm = redm[0];
#pragma unroll
    for (int w = 1; w < 8; w++) bm = fmaxf(bm, redm[w]);

    float e0 = __expf(s0 - bm);
    float e1 = __expf(s1 - bm);
    attn[tid]       = e0;
    attn[tid + 256] = e1;

    float su = e0 + e1;
#pragma unroll
    for (int o = 16; o > 0; o >>= 1) su += __shfl_xor_sync(0xffffffffu, su, o);
    if (lane == 0) reds[warp] = su;
    __syncthreads();
    float tot = 0.f;
#pragma unroll
    for (int w = 0; w < 8; w++) tot += reds[w];
    float inv = 1.f / tot;

    const int t0 = q * 128;
    const float* base = ip + ((size_t)b * TLEN + t0) * DDIM + tid;
    float acc = 0.f;
#pragma unroll 8
    for (int t = 0; t < 128; t++)
        acc = fmaf(attn[t0 + t], base[(size_t)t * DDIM], acc);

    g_part[q][b][tid] = acc * inv;
}

__global__ __launch_bounds__(256) void combine_kernel(float* __restrict__ out)
{
    const int b = blockIdx.x;
    const int d = threadIdx.x;
    out[(size_t)b * DDIM + d] = g_part[0][b][d] + g_part[1][b][d]
                              + g_part[2][b][d] + g_part[3][b][d];
}

// ---------------------------------------------------------------------------
extern "C" void kernel_launch(void* const* d_in, const int* in_sizes, int n_in,
                              void* d_out, int out_size)
{
    const float* ip   = (const float*)d_in[0];
    const float* W    = (const float*)d_in[1];
    const float* bias = (const float*)d_in[2];
    const float* ctx  = (const float*)d_in[3];
    float* out = (float*)d_out;

    cudaFuncSetAttribute(scores_kernel,
                         cudaFuncAttributeMaxDynamicSharedMemorySize, SMEM_BYTES);

    scores_kernel<<<NROWS / BM, NTHREADS, SMEM_BYTES>>>(ip, W, bias, ctx);
    dim3 gp(BATCH, 4);
    out_partial_kernel<<<gp, 256>>>(ip);
    combine_kernel<<<BATCH, 256>>>(out);
}

// round 6
// speedup vs baseline: 3.0468x; 1.2524x over previous
#include <cuda_runtime.h>
#include <cuda_fp16.h>
#include <cuda_bf16.h>
#include <cstdint>

// Problem constants
#define BATCH 256
#define TLEN  512
#define DDIM  256
#define NROWS (BATCH * TLEN)

// GEMM tiling: fp16 m16n8k16 path, K-chunks of 64
#define BM 128
#define BN 256
#define BKH 64                      // K elems per chunk (64 fp16 = 128B rows)
#define NTHREADS 512
#define NCHUNK (DDIM / BKH)         // 4
#define BSTAGES 3

// smem layout (dynamic), bytes
#define SB_STAGE (BN * 128)                 // 32768 (256 rows x 128B fp16)
#define SA_TILE  (BM * 128)                 // 16384 (128 rows x 128B fp16)
#define OFF_B    0
#define OFF_A    (BSTAGES * SB_STAGE)       // 98304
#define OFF_SPART (OFF_A + 2 * SA_TILE)     // 131072
#define SMEM_BYTES (OFF_SPART + 16 * 64 * 4)  // 135168

// scratch (static device arrays: no allocation)
__device__ float  g_scores[NROWS];
__device__ float  g_part[4][BATCH][DDIM];
__device__ __half g_Wh[DDIM * DDIM];        // fp16 copy of W (128KB)

__device__ __forceinline__ void cpa16(void* smem, const void* gmem) {
    unsigned s = (unsigned)__cvta_generic_to_shared(smem);
    asm volatile("cp.async.cg.shared.global [%0], [%1], 16;\n" :: "r"(s), "l"(gmem));
}
__device__ __forceinline__ void cpa_commit() {
    asm volatile("cp.async.commit_group;\n");
}
template <int N>
__device__ __forceinline__ void cpa_wait() {
    asm volatile("cp.async.wait_group %0;\n" :: "n"(N));
}

__device__ __forceinline__ void ldsm_x4(unsigned r[4], unsigned addr) {
    asm volatile(
        "ldmatrix.sync.aligned.m8n8.x4.shared.b16 {%0,%1,%2,%3}, [%4];"
        : "=r"(r[0]), "=r"(r[1]), "=r"(r[2]), "=r"(r[3]) : "r"(addr));
}
__device__ __forceinline__ void ldsm_x2(unsigned& r0, unsigned& r1, unsigned addr) {
    asm volatile(
        "ldmatrix.sync.aligned.m8n8.x2.shared.b16 {%0,%1}, [%2];"
        : "=r"(r0), "=r"(r1) : "r"(addr));
}

__device__ __forceinline__ void mma_f16(float c[4],
                                        unsigned a0, unsigned a1, unsigned a2, unsigned a3,
                                        unsigned b0, unsigned b1) {
    asm volatile(
        "mma.sync.aligned.m16n8k16.row.col.f32.f16.f16.f32 "
        "{%0,%1,%2,%3}, {%4,%5,%6,%7}, {%8,%9}, {%0,%1,%2,%3};\n"
        : "+f"(c[0]), "+f"(c[1]), "+f"(c[2]), "+f"(c[3])
        : "r"(a0), "r"(a1), "r"(a2), "r"(a3), "r"(b0), "r"(b1));
}

__device__ __forceinline__ float tanh_fast(float x) {
    x = fminf(fmaxf(x, -15.f), 15.f);
    float e = __expf(2.f * x);
    return __fdividef(e - 1.f, e + 1.f);
}

__device__ __forceinline__ unsigned pack_h2(float a, float b) {
    __half2 h = __floats2half2_rn(a, b);
    return *reinterpret_cast<unsigned*>(&h);
}

// ---------------------------------------------------------------------------
// Kernel 0: W -> fp16 (one-time, 128KB)
// ---------------------------------------------------------------------------
__global__ __launch_bounds__(256) void convert_w_kernel(const float* __restrict__ W)
{
    int i = (blockIdx.x * 256 + threadIdx.x) * 4;
    float4 v = *(const float4*)(W + i);
    unsigned u0 = pack_h2(v.x, v.y);
    unsigned u1 = pack_h2(v.z, v.w);
    *(uint2*)(g_Wh + i) = make_uint2(u0, u1);
}

// ---------------------------------------------------------------------------
// Kernel 1: fused fp16 tensor-core GEMM (fp32 accum) + tanh + context dot.
// A converted in-flight (LDG fp32 -> regs -> fp16 STS), W from g_Wh via
// cp.async ring. One barrier per K64-chunk (4 total).
// ---------------------------------------------------------------------------
__global__ void __launch_bounds__(NTHREADS, 1) scores_kernel(
    const float* __restrict__ ip,    // [NROWS, 256]
    const float* __restrict__ bias,  // [256]
    const float* __restrict__ ctx)   // [256]
{
    extern __shared__ char smem[];
    __shared__ float sbias[BN];
    __shared__ float sctx[BN];

    const int tid   = threadIdx.x;
    const int warp  = tid >> 5;
    const int lane  = tid & 31;
    const int g     = lane >> 2;
    const int tg    = lane & 3;
    const int mhalf = warp >> 3;        // 0..1
    const int nwarp = warp & 7;         // 0..7
    const int wn    = nwarp * 32;
    const int rowBase = blockIdx.x * BM;

    if (tid < BN) { sbias[tid] = bias[tid]; sctx[tid] = ctx[tid]; }

    // LDSM lane-constant addressing (identical pattern to tf32 path)
    const int s7  = lane & 7;
    const int c0a = lane >> 4;           // A: lanes 16-31 -> khi 16B chunk
    const unsigned aRowOff =
        (unsigned)((mhalf * 64 + ((lane >> 3) & 1) * 8 + s7) * 128);
    const int cbm = (lane >> 3) & 1;     // B: lanes 8-15 -> khi chunk
    const unsigned bRowOff0 = (unsigned)((wn + s7) * 128);

    const unsigned smem_base = (unsigned)__cvta_generic_to_shared(smem);

    // A conversion mapping: thread owns row (tid>>2), 16-float quarter (tid&3)
    const int aRow = tid >> 2;
    const int aQ   = tid & 3;
    const float* aSrc = ip + (size_t)(rowBase + aRow) * DDIM + aQ * 16;
    char* aDstRow = smem + OFF_A;        // + (c&1)*SA_TILE at use site
    const int aChunk0 = (2 * aQ) ^ (aRow & 7);
    const int aChunk1 = (2 * aQ + 1) ^ (aRow & 7);

    float acc[4][4][4];
#pragma unroll
    for (int mt = 0; mt < 4; mt++)
#pragma unroll
        for (int nt = 0; nt < 4; nt++)
#pragma unroll
            for (int i = 0; i < 4; i++) acc[mt][nt][i] = 0.f;

    // B stage loader: K64-chunk c -> ring slot c % 3 (from fp16 g_Wh)
    auto issueB = [&](int c) {
        char* sB = smem + OFF_B + (c % BSTAGES) * SB_STAGE;
        const char* src = (const char*)g_Wh + c * 128;   // row segment
#pragma unroll
        for (int i = 0; i < 4; i++) {
            int f = tid + i * NTHREADS;
            int r = f >> 3, cc = f & 7;
            cpa16(sB + r * 128 + (((cc) ^ (r & 7)) << 4),
                  src + (size_t)r * 512 + cc * 16);
        }
    };

    // prologue: A chunk 0 into regs; B chunks 0,1 staged
    float4 areg[4];
#pragma unroll
    for (int i = 0; i < 4; i++) areg[i] = *(const float4*)(aSrc + i * 4);
    issueB(0); cpa_commit();
    issueB(1); cpa_commit();

    for (int c = 0; c < NCHUNK; c++) {
        // STS this chunk's A (fp16, swizzled) from regs
        {
            char* dst = aDstRow + (c & 1) * SA_TILE + aRow * 128;
            uint4 u0, u1;
            u0.x = pack_h2(areg[0].x, areg[0].y);
            u0.y = pack_h2(areg[0].z, areg[0].w);
            u0.z = pack_h2(areg[1].x, areg[1].y);
            u0.w = pack_h2(areg[1].z, areg[1].w);
            u1.x = pack_h2(areg[2].x, areg[2].y);
            u1.y = pack_h2(areg[2].z, areg[2].w);
            u1.z = pack_h2(areg[3].x, areg[3].y);
            u1.w = pack_h2(areg[3].z, areg[3].w);
            *(uint4*)(dst + aChunk0 * 16) = u0;
            *(uint4*)(dst + aChunk1 * 16) = u1;
        }

        cpa_wait<1>();       // B chunk c resident
        __syncthreads();     // A16 visible to all; B slot (c-1)%3 reusable

        // prefetch next A chunk into regs (latency hides under compute)
        if (c + 1 < NCHUNK) {
#pragma unroll
            for (int i = 0; i < 4; i++)
                areg[i] = *(const float4*)(aSrc + (c + 1) * BKH + i * 4);
        }
        if (c + 2 < NCHUNK) issueB(c + 2);
        cpa_commit();        // uniform group counting

        const unsigned sAu = smem_base + OFF_A + (unsigned)((c & 1) * SA_TILE);
        const unsigned sBu = smem_base + OFF_B + (unsigned)((c % BSTAGES) * SB_STAGE);

#pragma unroll
        for (int ks = 0; ks < 4; ks++) {
            const int kc = ks * 2;       // 16B-chunk index of klo
            unsigned a[4][4];
#pragma unroll
            for (int mt = 0; mt < 4; mt++) {
                unsigned addr = sAu + aRowOff + (unsigned)(mt * 2048)
                              + (unsigned)(((kc + c0a) ^ s7) << 4);
                ldsm_x4(a[mt], addr);
            }
#pragma unroll
            for (int nt = 0; nt < 4; nt++) {
                unsigned addr = sBu + bRowOff0 + (unsigned)(nt * 8 * 128)
                              + (unsigned)(((kc + cbm) ^ s7) << 4);
                unsigned b0, b1;
                ldsm_x2(b0, b1, addr);
#pragma unroll
                for (int mt = 0; mt < 4; mt++)
                    mma_f16(acc[mt][nt], a[mt][0], a[mt][1], a[mt][2], a[mt][3], b0, b1);
            }
        }
    }

    // ---- epilogue: row score = sum_cols tanh(acc + bias) * ctx ----
    float rs[8];
#pragma unroll
    for (int i = 0; i < 8; i++) rs[i] = 0.f;

#pragma unroll
    for (int nt = 0; nt < 4; nt++) {
        int col = wn + nt * 8 + 2 * tg;
        float b0 = sbias[col], b1 = sbias[col + 1];
        float c0 = sctx[col],  c1 = sctx[col + 1];
#pragma unroll
        for (int mt = 0; mt < 4; mt++) {
            rs[2 * mt]     += tanh_fast(acc[mt][nt][0] + b0) * c0
                            + tanh_fast(acc[mt][nt][1] + b1) * c1;
            rs[2 * mt + 1] += tanh_fast(acc[mt][nt][2] + b0) * c0
                            + tanh_fast(acc[mt][nt][3] + b1) * c1;
        }
    }
#pragma unroll
    for (int off = 1; off <= 2; off <<= 1)
#pragma unroll
        for (int i = 0; i < 8; i++)
            rs[i] += __shfl_xor_sync(0xffffffffu, rs[i], off);

    float* spart = (float*)(smem + OFF_SPART);   // [16 warps][64 rows]
    __syncthreads();
    if (tg == 0) {
#pragma unroll
        for (int mt = 0; mt < 4; mt++) {
            spart[warp * 64 + mt * 16 + g]     = rs[2 * mt];
            spart[warp * 64 + mt * 16 + 8 + g] = rs[2 * mt + 1];
        }
    }
    __syncthreads();
    if (tid < BM) {
        int mh = tid >> 6, row = tid & 63;
        float s = 0.f;
#pragma unroll
        for (int w = 0; w < 8; w++) s += spart[(mh * 8 + w) * 64 + row];
        g_scores[rowBase + tid] = s;
    }
}

// ---------------------------------------------------------------------------
// Kernel 2: softmax (redundant per t-slice, cheap) + partial weighted sums
// ---------------------------------------------------------------------------
__global__ __launch_bounds__(256) void out_partial_kernel(
    const float* __restrict__ ip)
{
    __shared__ float attn[TLEN];
    __shared__ float redm[8];
    __shared__ float reds[8];

    const int b = blockIdx.x;
    const int q = blockIdx.y;
    const int tid = threadIdx.x;
    const int warp = tid >> 5;
    const int lane = tid & 31;

    const float* sc = g_scores + (size_t)b * TLEN;
    float s0 = sc[tid];
    float s1 = sc[tid + 256];

    float m = fmaxf(s0, s1);
#pragma unroll
    for (int o = 16; o > 0; o >>= 1) m = fmaxf(m, __shfl_xor_sync(0xffffffffu, m, o));
    if (lane == 0) redm[warp] = m;
    __syncthreads();
    float bm = redm[0];
#pragma unroll
    for (int w = 1; w < 8; w++) bm = fmaxf(bm, redm[w]);

    float e0 = __expf(s0 - bm);
    float e1 = __expf(s1 - bm);
    attn[tid]       = e0;
    attn[tid + 256] = e1;

    float su = e0 + e1;
#pragma unroll
    for (int o = 16; o > 0; o >>= 1) su += __shfl_xor_sync(0xffffffffu, su, o);
    if (lane == 0) reds[warp] = su;
    __syncthreads();
    float tot = 0.f;
#pragma unroll
    for (int w = 0; w < 8; w++) tot += reds[w];
    float inv = 1.f / tot;

    const int t0 = q * 128;
    const float* base = ip + ((size_t)b * TLEN + t0) * DDIM + tid;
    float acc = 0.f;
#pragma unroll 8
    for (int t = 0; t < 128; t++)
        acc = fmaf(attn[t0 + t], base[(size_t)t * DDIM], acc);

    g_part[q][b][tid] = acc * inv;
}

__global__ __launch_bounds__(256) void combine_kernel(float* __restrict__ out)
{
    const int b = blockIdx.x;
    const int d = threadIdx.x;
    out[(size_t)b * DDIM + d] = g_part[0][b][d] + g_part[1][b][d]
                              + g_part[2][b][d] + g_part[3][b][d];
}

// ---------------------------------------------------------------------------
extern "C" void kernel_launch(void* const* d_in, const int* in_sizes, int n_in,
                              void* d_out, int out_size)
{
    const float* ip   = (const float*)d_in[0];
    const float* W    = (const float*)d_in[1];
    const float* bias = (const float*)d_in[2];
    const float* ctx  = (const float*)d_in[3];
    float* out = (float*)d_out;

    cudaFuncSetAttribute(scores_kernel,
                         cudaFuncAttributeMaxDynamicSharedMemorySize, SMEM_BYTES);

    convert_w_kernel<<<DDIM * DDIM / 1024, 256>>>(W);
    scores_kernel<<<NROWS / BM, NTHREADS, SMEM_BYTES>>>(ip, bias, ctx);
    dim3 gp(BATCH, 4);
    out_partial_kernel<<<gp, 256>>>(ip);
    combine_kernel<<<BATCH, 256>>>(out);
}

// round 7
// speedup vs baseline: 3.2312x; 1.0605x over previous
#include <cuda_runtime.h>
#include <cuda_fp16.h>
#include <cuda_bf16.h>
#include <cstdint>

// Problem constants
#define BATCH 256
#define TLEN  512
#define DDIM  256
#define NROWS (BATCH * TLEN)

// GEMM tiling: fp16 m16n8k16, K-chunks of 64, persistent CTAs, W resident
#define BM 128
#define BN 256
#define BKH 64
#define NTHREADS 512
#define NTILES (NROWS / BM)          // 1024
#define GRID_SCORES 148
#define OUTSPLIT 8

// smem layout (dynamic), bytes
#define SB_SLAB  (BN * 128)                  // 32768 per k-slab (256 rows x 128B)
#define OFF_B    0                           // 4 slabs = 131072
#define SA_TILE  (BM * 128)                  // 16384
#define OFF_A    (4 * SB_SLAB)               // 131072
#define OFF_SPART (OFF_A + 2 * SA_TILE)      // 163840
#define SMEM_BYTES (OFF_SPART + 16 * 64 * 4) // 167936

// scratch (static device arrays: no allocation)
__device__ float  g_scores[NROWS];
__device__ float  g_part[OUTSPLIT][BATCH][DDIM];
__device__ __half g_Wh[DDIM * DDIM];         // fp16 W (128KB)

__device__ __forceinline__ void cpa16(void* smem, const void* gmem) {
    unsigned s = (unsigned)__cvta_generic_to_shared(smem);
    asm volatile("cp.async.cg.shared.global [%0], [%1], 16;\n" :: "r"(s), "l"(gmem));
}
__device__ __forceinline__ void cpa_commit() {
    asm volatile("cp.async.commit_group;\n");
}
template <int N>
__device__ __forceinline__ void cpa_wait() {
    asm volatile("cp.async.wait_group %0;\n" :: "n"(N));
}

__device__ __forceinline__ void ldsm_x4(unsigned r[4], unsigned addr) {
    asm volatile(
        "ldmatrix.sync.aligned.m8n8.x4.shared.b16 {%0,%1,%2,%3}, [%4];"
        : "=r"(r[0]), "=r"(r[1]), "=r"(r[2]), "=r"(r[3]) : "r"(addr));
}
__device__ __forceinline__ void ldsm_x2(unsigned& r0, unsigned& r1, unsigned addr) {
    asm volatile(
        "ldmatrix.sync.aligned.m8n8.x2.shared.b16 {%0,%1}, [%2];"
        : "=r"(r0), "=r"(r1) : "r"(addr));
}

__device__ __forceinline__ void mma_f16(float c[4],
                                        unsigned a0, unsigned a1, unsigned a2, unsigned a3,
                                        unsigned b0, unsigned b1) {
    asm volatile(
        "mma.sync.aligned.m16n8k16.row.col.f32.f16.f16.f32 "
        "{%0,%1,%2,%3}, {%4,%5,%6,%7}, {%8,%9}, {%0,%1,%2,%3};\n"
        : "+f"(c[0]), "+f"(c[1]), "+f"(c[2]), "+f"(c[3])
        : "r"(a0), "r"(a1), "r"(a2), "r"(a3), "r"(b0), "r"(b1));
}

__device__ __forceinline__ float tanh_fast(float x) {
    x = fminf(fmaxf(x, -15.f), 15.f);
    float e = __expf(2.f * x);
    return __fdividef(e - 1.f, e + 1.f);
}

__device__ __forceinline__ unsigned pack_h2(float a, float b) {
    __half2 h = __floats2half2_rn(a, b);
    return *reinterpret_cast<unsigned*>(&h);
}

// ---------------------------------------------------------------------------
// Kernel 0: W -> fp16
// ---------------------------------------------------------------------------
__global__ __launch_bounds__(256) void convert_w_kernel(const float* __restrict__ W)
{
    int i = (blockIdx.x * 256 + threadIdx.x) * 4;
    float4 v = *(const float4*)(W + i);
    *(uint2*)(g_Wh + i) = make_uint2(pack_h2(v.x, v.y), pack_h2(v.z, v.w));
}

// ---------------------------------------------------------------------------
// Kernel 1: persistent fused fp16 GEMM + tanh + context dot.
// W resident in smem (loaded once); A converted in-flight per chunk.
// ---------------------------------------------------------------------------
__global__ void __launch_bounds__(NTHREADS, 1) scores_kernel(
    const float* __restrict__ ip,    // [NROWS, 256]
    const float* __restrict__ bias,  // [256]
    const float* __restrict__ ctx)   // [256]
{
    extern __shared__ char smem[];
    __shared__ float sbias[BN];
    __shared__ float sctx[BN];

    const int tid   = threadIdx.x;
    const int warp  = tid >> 5;
    const int lane  = tid & 31;
    const int g     = lane >> 2;
    const int tg    = lane & 3;
    const int mhalf = warp >> 3;        // 0..1
    const int nwarp = warp & 7;         // 0..7
    const int wn    = nwarp * 32;

    if (tid < BN) { sbias[tid] = bias[tid]; sctx[tid] = ctx[tid]; }

    // LDSM lane-constant addressing
    const int s7  = lane & 7;
    const int c0a = lane >> 4;
    const unsigned aRowOff =
        (unsigned)((mhalf * 64 + ((lane >> 3) & 1) * 8 + s7) * 128);
    const int cbm = (lane >> 3) & 1;
    const unsigned bRowOff0 = (unsigned)((wn + s7) * 128);

    const unsigned smem_base = (unsigned)__cvta_generic_to_shared(smem);

    // A conversion mapping: thread owns row (tid>>2), quarter (tid&3)
    const int aRow = tid >> 2;
    const int aQ   = tid & 3;
    const int aChunk0 = (2 * aQ) ^ (aRow & 7);
    const int aChunk1 = (2 * aQ + 1) ^ (aRow & 7);

    // persistent work list: tiles blockIdx.x + j*gridDim.x
    const int my_ntiles = (NTILES - blockIdx.x + gridDim.x - 1) / gridDim.x;
    const int total = my_ntiles * 4;     // chunk-steps

    auto aSrcFor = [&](int q) -> const float* {
        int tile = blockIdx.x + (q >> 2) * (int)gridDim.x;
        return ip + ((size_t)tile * BM + aRow) * DDIM + aQ * 16 + (q & 3) * BKH;
    };

    // prefetch A(0) while B streams in
    float4 areg[4];
    {
        const float* p = aSrcFor(0);
#pragma unroll
        for (int i = 0; i < 4; i++) areg[i] = *(const float4*)(p + i * 4);
    }

    // load ALL of W into smem (4 swizzled k-slabs), 16 cpa16 per thread
#pragma unroll
    for (int i = 0; i < 16; i++) {
        int f = tid + i * NTHREADS;
        int slab = f >> 11;
        int rem  = f & 2047;
        int r = rem >> 3, cc = rem & 7;
        cpa16(smem + OFF_B + slab * SB_SLAB + r * 128 + ((cc ^ (r & 7)) << 4),
              (const char*)g_Wh + (size_t)r * 512 + slab * 128 + cc * 16);
    }
    cpa_commit();
    cpa_wait<0>();
    __syncthreads();

    float acc[4][4][4];
#pragma unroll
    for (int mt = 0; mt < 4; mt++)
#pragma unroll
        for (int nt = 0; nt < 4; nt++)
#pragma unroll
            for (int i = 0; i < 4; i++) acc[mt][nt][i] = 0.f;

    for (int q = 0; q < total; q++) {
        // STS A(q) fp16 swizzled into buffer q&1
        {
            char* dst = smem + OFF_A + (q & 1) * SA_TILE + aRow * 128;
            uint4 u0, u1;
            u0.x = pack_h2(areg[0].x, areg[0].y);
            u0.y = pack_h2(areg[0].z, areg[0].w);
            u0.z = pack_h2(areg[1].x, areg[1].y);
            u0.w = pack_h2(areg[1].z, areg[1].w);
            u1.x = pack_h2(areg[2].x, areg[2].y);
            u1.y = pack_h2(areg[2].z, areg[2].w);
            u1.z = pack_h2(areg[3].x, areg[3].y);
            u1.w = pack_h2(areg[3].z, areg[3].w);
            *(uint4*)(dst + aChunk0 * 16) = u0;
            *(uint4*)(dst + aChunk1 * 16) = u1;
        }
        __syncthreads();

        // prefetch A(q+1)
        if (q + 1 < total) {
            const float* p = aSrcFor(q + 1);
#pragma unroll
            for (int i = 0; i < 4; i++) areg[i] = *(const float4*)(p + i * 4);
        }

        const unsigned sAu = smem_base + OFF_A + (unsigned)((q & 1) * SA_TILE);
        const unsigned sBu = smem_base + OFF_B + (unsigned)((q & 3) * SB_SLAB);

#pragma unroll
        for (int ks = 0; ks < 4; ks++) {
            const int kc = ks * 2;
            unsigned a[4][4];
#pragma unroll
            for (int mt = 0; mt < 4; mt++) {
                unsigned addr = sAu + aRowOff + (unsigned)(mt * 2048)
                              + (unsigned)(((kc + c0a) ^ s7) << 4);
                ldsm_x4(a[mt], addr);
            }
#pragma unroll
            for (int nt = 0; nt < 4; nt++) {
                unsigned addr = sBu + bRowOff0 + (unsigned)(nt * 8 * 128)
                              + (unsigned)(((kc + cbm) ^ s7) << 4);
                unsigned b0, b1;
                ldsm_x2(b0, b1, addr);
#pragma unroll
                for (int mt = 0; mt < 4; mt++)
                    mma_f16(acc[mt][nt], a[mt][0], a[mt][1], a[mt][2], a[mt][3], b0, b1);
            }
        }

        if ((q & 3) == 3) {
            // ---- tile epilogue ----
            const int tile = blockIdx.x + (q >> 2) * (int)gridDim.x;
            float rs[8];
#pragma unroll
            for (int i = 0; i < 8; i++) rs[i] = 0.f;

#pragma unroll
            for (int nt = 0; nt < 4; nt++) {
                int col = wn + nt * 8 + 2 * tg;
                float b0 = sbias[col], b1 = sbias[col + 1];
                float c0 = sctx[col],  c1 = sctx[col + 1];
#pragma unroll
                for (int mt = 0; mt < 4; mt++) {
                    rs[2 * mt]     += tanh_fast(acc[mt][nt][0] + b0) * c0
                                    + tanh_fast(acc[mt][nt][1] + b1) * c1;
                    rs[2 * mt + 1] += tanh_fast(acc[mt][nt][2] + b0) * c0
                                    + tanh_fast(acc[mt][nt][3] + b1) * c1;
                }
            }
#pragma unroll
            for (int off = 1; off <= 2; off <<= 1)
#pragma unroll
                for (int i = 0; i < 8; i++)
                    rs[i] += __shfl_xor_sync(0xffffffffu, rs[i], off);

            float* spart = (float*)(smem + OFF_SPART);
            if (tg == 0) {
#pragma unroll
                for (int mt = 0; mt < 4; mt++) {
                    spart[warp * 64 + mt * 16 + g]     = rs[2 * mt];
                    spart[warp * 64 + mt * 16 + 8 + g] = rs[2 * mt + 1];
                }
            }
            __syncthreads();
            if (tid < BM) {
                int mh = tid >> 6, row = tid & 63;
                float s = 0.f;
#pragma unroll
                for (int w = 0; w < 8; w++) s += spart[(mh * 8 + w) * 64 + row];
                g_scores[(size_t)tile * BM + tid] = s;
            }
            // reset accumulators for next tile
#pragma unroll
            for (int mt = 0; mt < 4; mt++)
#pragma unroll
                for (int nt = 0; nt < 4; nt++)
#pragma unroll
                    for (int i = 0; i < 4; i++) acc[mt][nt][i] = 0.f;
        }
    }
}

// ---------------------------------------------------------------------------
// Kernel 2: softmax (redundant per t-slice, cheap) + partial weighted sums
// ---------------------------------------------------------------------------
__global__ __launch_bounds__(256) void out_partial_kernel(
    const float* __restrict__ ip)
{
    __shared__ float attn[TLEN];
    __shared__ float redm[8];
    __shared__ float reds[8];

    const int b = blockIdx.x;
    const int q = blockIdx.y;
    const int tid = threadIdx.x;
    const int warp = tid >> 5;
    const int lane = tid & 31;

    const float* sc = g_scores + (size_t)b * TLEN;
    float s0 = sc[tid];
    float s1 = sc[tid + 256];

    float m = fmaxf(s0, s1);
#pragma unroll
    for (int o = 16; o > 0; o >>= 1) m = fmaxf(m, __shfl_xor_sync(0xffffffffu, m, o));
    if (lane == 0) redm[warp] = m;
    __syncthreads();
    float bm = redm[0];
#pragma unroll
    for (int w = 1; w < 8; w++) bm = fmaxf(bm, redm[w]);

    float e0 = __expf(s0 - bm);
    float e1 = __expf(s1 - bm);
    attn[tid]       = e0;
    attn[tid + 256] = e1;

    float su = e0 + e1;
#pragma unroll
    for (int o = 16; o > 0; o >>= 1) su += __shfl_xor_sync(0xffffffffu, su, o);
    if (lane == 0) reds[warp] = su;
    __syncthreads();
    float tot = 0.f;
#pragma unroll
    for (int w = 0; w < 8; w++) tot += reds[w];
    float inv = 1.f / tot;

    const int TPB = TLEN / OUTSPLIT;     // 64
    const int t0 = q * TPB;
    const float* base = ip + ((size_t)b * TLEN + t0) * DDIM + tid;
    float acc = 0.f;
#pragma unroll 8
    for (int t = 0; t < TPB; t++)
        acc = fmaf(attn[t0 + t], base[(size_t)t * DDIM], acc);

    g_part[q][b][tid] = acc * inv;
}

__global__ __launch_bounds__(256) void combine_kernel(float* __restrict__ out)
{
    const int b = blockIdx.x;
    const int d = threadIdx.x;
    float s = 0.f;
#pragma unroll
    for (int q = 0; q < OUTSPLIT; q++) s += g_part[q][b][d];
    out[(size_t)b * DDIM + d] = s;
}

// ---------------------------------------------------------------------------
extern "C" void kernel_launch(void* const* d_in, const int* in_sizes, int n_in,
                              void* d_out, int out_size)
{
    const float* ip   = (const float*)d_in[0];
    const float* W    = (const float*)d_in[1];
    const float* bias = (const float*)d_in[2];
    const float* ctx  = (const float*)d_in[3];
    float* out = (float*)d_out;

    cudaFuncSetAttribute(scores_kernel,
                         cudaFuncAttributeMaxDynamicSharedMemorySize, SMEM_BYTES);

    convert_w_kernel<<<DDIM * DDIM / 1024, 256>>>(W);
    scores_kernel<<<GRID_SCORES, NTHREADS, SMEM_BYTES>>>(ip, bias, ctx);
    dim3 gp(BATCH, OUTSPLIT);
    out_partial_kernel<<<gp, 256>>>(ip);
    combine_kernel<<<BATCH, 256>>>(out);
}